// round 17
// baseline (speedup 1.0000x reference)
#include <cuda_runtime.h>
#include <cuda_bf16.h>
#include <cuda_fp16.h>
#include <cstdint>

#define NMAX 100000
#define D 128

typedef unsigned long long ull;

// Scratch (device globals: allocation-free per harness rules)
__device__ __align__(256) uint2 g_x16[(size_t)NMAX * 32];   // fp16 plane of x
__device__ __align__(256) uint2 g_h16[(size_t)NMAX * 32];   // fp16 plane of h (layer-1 out)
__device__ __align__(256) uint2 g_agg16[(size_t)NMAX * 32]; // fp16 plane of mean-agg
__device__ __align__(16)  char  g_W16[131072];              // fp16 weights [layer][kc][n][64]
__device__ int   g_deg[NMAX];
__device__ int   g_off[NMAX + 1];
__device__ int   g_cur[NMAX];
__device__ int   g_esrc[1600000 + 1024];                    // src sorted by dst (CSR)
__device__ float g_inv[NMAX];
__device__ int   g_part[256];
__device__ int   g_pbase[256];
__device__ int   g_tilecnt[2048];                           // per-layer per-tile agg counters
__device__ int   g_idx32;

// ---------------------------------------------------------------------------
__device__ __forceinline__ uint32_t smem_u32(const void* p) {
    uint32_t a;
    asm("{ .reg .u64 t; cvta.to.shared.u64 t, %1; cvt.u32.u64 %0, t; }" : "=r"(a) : "l"(p));
    return a;
}

__device__ __forceinline__ void cpasync16(uint32_t s, const void* g, int sz) {
    asm volatile("cp.async.cg.shared.global [%0], [%1], 16, %2;"
                 :: "r"(s), "l"(g), "r"(sz) : "memory");
}

#define LDSM4(r0, r1, r2, r3, addr)                                           \
    asm volatile("ldmatrix.sync.aligned.m8n8.x4.shared.b16 {%0,%1,%2,%3},[%4];" \
                 : "=r"(r0), "=r"(r1), "=r"(r2), "=r"(r3) : "r"(addr))

#define MMA_F16(c, a0, a1, a2, a3, b0, b1)                                    \
    asm volatile("mma.sync.aligned.m16n8k16.row.col.f32.f16.f16.f32 "         \
                 "{%0,%1,%2,%3},{%4,%5,%6,%7},{%8,%9},{%0,%1,%2,%3};"         \
                 : "+f"((c)[0]), "+f"((c)[1]), "+f"((c)[2]), "+f"((c)[3])     \
                 : "r"(a0), "r"(a1), "r"(a2), "r"(a3), "r"(b0), "r"(b1))

// ---------------------------------------------------------------------------
__global__ void detect_kernel(const void* eidx) {
    const ull* p = (const ull*)eidx;
    int is32 = 0;
    #pragma unroll
    for (int i = 0; i < 4; i++)
        if (p[i] >= (1ULL << 32)) is32 = 1;
    g_idx32 = is32;
}

__device__ __forceinline__ int load_idx(const void* eidx, long long pos) {
    if (g_idx32) return ((const int*)eidx)[pos];
    return (int)(((const long long*)eidx)[pos]);
}

// fp32 -> fp16 plane conversion.
__global__ void tohalf_kernel(const float4* __restrict__ src,
                              uint2* __restrict__ dst, int n4) {
    int t = blockIdx.x * blockDim.x + threadIdx.x;
    if (t >= n4) return;
    float4 v = src[t];
    __half2 h0 = __floats2half2_rn(v.x, v.y);
    __half2 h1 = __floats2half2_rn(v.z, v.w);
    dst[t] = make_uint2(*(uint32_t*)&h0, *(uint32_t*)&h1);
}

// fp16 weight image: [layer][kc][n][64 halves], B[n][k] = W[k][n].
__global__ void wconv16_kernel(const float* __restrict__ Wl1, const float* __restrict__ Wr1,
                               const float* __restrict__ Wl2, const float* __restrict__ Wr2) {
    int unit = blockIdx.x * 256 + threadIdx.x;   // 1024 units
    if (unit >= 1024) return;
    int layer = unit >> 9;
    int kc = (unit >> 7) & 3;
    int n = unit & 127;
    const float* Wsrc = (layer == 0) ? ((kc < 2) ? Wl1 : Wr1)
                                     : ((kc < 2) ? Wl2 : Wr2);
    int kbase = (kc & 1) * 64;
    uint32_t buf[32];
    #pragma unroll
    for (int j = 0; j < 32; j++) {
        float v0 = Wsrc[(kbase + 2 * j) * 128 + n];
        float v1 = Wsrc[(kbase + 2 * j + 1) * 128 + n];
        __half2 h = __floats2half2_rn(v0, v1);
        buf[j] = *(uint32_t*)&h;
    }
    char* dst = g_W16 + (((size_t)layer * 4 + kc) * 128 + n) * 128;
    #pragma unroll
    for (int q = 0; q < 8; q++)
        ((uint4*)dst)[q] = make_uint4(buf[4 * q], buf[4 * q + 1],
                                      buf[4 * q + 2], buf[4 * q + 3]);
}

// 4 edges per thread (R13 form — atomic-rate bound, wider unroll was neutral).
__global__ void deg_kernel(const void* eidx, int nE) {
    int t = blockIdx.x * blockDim.x + threadIdx.x;
    int ngrp = nE >> 2;
    if (t < ngrp) {
        int d0, d1, d2, d3;
        if (g_idx32) {
            int4 v = ((const int4*)eidx)[ngrp + t];
            d0 = v.x; d1 = v.y; d2 = v.z; d3 = v.w;
        } else {
            longlong2 v0 = ((const longlong2*)eidx)[(nE >> 1) + t * 2];
            longlong2 v1 = ((const longlong2*)eidx)[(nE >> 1) + t * 2 + 1];
            d0 = (int)v0.x; d1 = (int)v0.y; d2 = (int)v1.x; d3 = (int)v1.y;
        }
        atomicAdd(&g_deg[d0], 1);
        atomicAdd(&g_deg[d1], 1);
        atomicAdd(&g_deg[d2], 1);
        atomicAdd(&g_deg[d3], 1);
    } else if (t == ngrp) {
        for (int e = ngrp * 4; e < nE; e++)
            atomicAdd(&g_deg[load_idx(eidx, (long long)nE + e)], 1);
    }
}

// Parallel 3-phase exclusive scan over degrees.
__global__ void blocksum_kernel(int nN) {
    __shared__ int ws[8];
    int t = threadIdx.x;
    int base = blockIdx.x * 1024 + t * 4;
    int s = 0;
    #pragma unroll
    for (int j = 0; j < 4; j++) {
        int i = base + j;
        if (i < nN) s += g_deg[i];
    }
    #pragma unroll
    for (int o = 16; o > 0; o >>= 1) s += __shfl_down_sync(~0u, s, o);
    if ((t & 31) == 0) ws[t >> 5] = s;
    __syncthreads();
    if (t < 8) {
        int v = ws[t];
        #pragma unroll
        for (int o = 4; o > 0; o >>= 1) v += __shfl_down_sync(0xff, v, o);
        if (t == 0) g_part[blockIdx.x] = v;
    }
}

__global__ void scanpart_kernel(int nb) {
    __shared__ int sm[128];
    int t = threadIdx.x;
    int v = (t < nb) ? g_part[t] : 0;
    sm[t] = v;
    __syncthreads();
    for (int o = 1; o < 128; o <<= 1) {
        int u = (t >= o) ? sm[t - o] : 0;
        __syncthreads();
        sm[t] += u;
        __syncthreads();
    }
    g_pbase[t] = (t == 0) ? 0 : sm[t - 1];
}

__global__ void offsets_kernel(int nN, int nE) {
    __shared__ int warp_tot[8];
    int t = threadIdx.x;
    int blk = blockIdx.x;
    int lane = t & 31, w = t >> 5;
    int base = blk * 1024 + t * 4;
    int d[4];
    int s = 0;
    #pragma unroll
    for (int j = 0; j < 4; j++) {
        int i = base + j;
        d[j] = (i < nN) ? g_deg[i] : 0;
        s += d[j];
    }
    int inc = s;
    #pragma unroll
    for (int o = 1; o < 32; o <<= 1) {
        int u = __shfl_up_sync(~0u, inc, o);
        if (lane >= o) inc += u;
    }
    if (lane == 31) warp_tot[w] = inc;
    __syncthreads();
    if (t < 8) {
        int v = warp_tot[t];
        #pragma unroll
        for (int o = 1; o < 8; o <<= 1) {
            int u = __shfl_up_sync(0xff, v, o);
            if (t >= o) v += u;
        }
        warp_tot[t] = v;
    }
    __syncthreads();
    int run = g_pbase[blk] + (inc - s) + ((w > 0) ? warp_tot[w - 1] : 0);
    #pragma unroll
    for (int j = 0; j < 4; j++) {
        int i = base + j;
        if (i < nN) {
            g_off[i] = run;
            g_cur[i] = run;
            g_inv[i] = 1.0f / (float)(d[j] > 0 ? d[j] : 1);
            run += d[j];
        }
    }
    if (blk == 0 && t == 0) g_off[nN] = nE;
}

// 4 edges per thread (R13 form).
__global__ void fill_kernel(const void* eidx, int nE) {
    int t = blockIdx.x * blockDim.x + threadIdx.x;
    int ngrp = nE >> 2;
    if (t < ngrp) {
        int s0, s1, s2, s3, d0, d1, d2, d3;
        if (g_idx32) {
            int4 sv = ((const int4*)eidx)[t];
            int4 dv = ((const int4*)eidx)[ngrp + t];
            s0 = sv.x; s1 = sv.y; s2 = sv.z; s3 = sv.w;
            d0 = dv.x; d1 = dv.y; d2 = dv.z; d3 = dv.w;
        } else {
            longlong2 a0 = ((const longlong2*)eidx)[t * 2];
            longlong2 a1 = ((const longlong2*)eidx)[t * 2 + 1];
            longlong2 b0 = ((const longlong2*)eidx)[(nE >> 1) + t * 2];
            longlong2 b1 = ((const longlong2*)eidx)[(nE >> 1) + t * 2 + 1];
            s0 = (int)a0.x; s1 = (int)a0.y; s2 = (int)a1.x; s3 = (int)a1.y;
            d0 = (int)b0.x; d1 = (int)b0.y; d2 = (int)b1.x; d3 = (int)b1.y;
        }
        g_esrc[atomicAdd(&g_cur[d0], 1)] = s0;
        g_esrc[atomicAdd(&g_cur[d1], 1)] = s1;
        g_esrc[atomicAdd(&g_cur[d2], 1)] = s2;
        g_esrc[atomicAdd(&g_cur[d3], 1)] = s3;
    } else if (t == ngrp) {
        for (int e = ngrp * 4; e < nE; e++) {
            int src = load_idx(eidx, e);
            int dst = load_idx(eidx, (long long)nE + e);
            g_esrc[atomicAdd(&g_cur[dst], 1)] = src;
        }
    }
}

// ---------------------------------------------------------------------------
__device__ __forceinline__ void acc4h(float4& a, uint2 v) {
    float2 p = __half22float2(*(__half2*)&v.x);
    float2 q = __half22float2(*(__half2*)&v.y);
    a.x += p.x; a.y += p.y; a.z += q.x; a.w += q.y;
}

// ---------------------------------------------------------------------------
// MERGED per-layer kernel: blocks [0, nAgg) aggregate (warp per node, full
// chip-wide gather MLP); blocks [nAgg, nAgg+tiles) run the double-buffered
// fp16 GEMM, doing x chunks first and spin-waiting on per-tile agg flags
// before staging mean chunks. HW dispatches CTAs in bid order -> agg first.
#define RS16 144
#define TILE16 (128 * RS16)            // 18432
#define BUF16 (2 * TILE16)             // A+B one stage
#define SM_TOTAL (2 * BUF16)           // 73728, 2 CTAs/SM

template <bool RELU, bool EMIT16>
__global__ void __launch_bounds__(256, 2)
layer_kernel(const uint2* __restrict__ plane16, int layer,
             const float* __restrict__ bias,
             float* __restrict__ out, uint32_t* __restrict__ out16,
             int nN, int nAgg) {
    extern __shared__ char smem[];
    const int tid = threadIdx.x;

    // ======================= AGG ROLE =======================
    if ((int)blockIdx.x < nAgg) {
        int wid = tid >> 5, lane = tid & 31;
        int node = blockIdx.x * 8 + wid;
        if (node < nN) {
            int beg = g_off[node], end = g_off[node + 1];
            float4 a0 = make_float4(0.f, 0.f, 0.f, 0.f);
            float4 a1 = a0;
            int i = beg;
            for (; i + 3 < end; i += 4) {
                int s0 = g_esrc[i], s1 = g_esrc[i + 1];
                int s2 = g_esrc[i + 2], s3 = g_esrc[i + 3];
                uint2 v0 = plane16[(size_t)s0 * 32 + lane];
                uint2 v1 = plane16[(size_t)s1 * 32 + lane];
                uint2 v2 = plane16[(size_t)s2 * 32 + lane];
                uint2 v3 = plane16[(size_t)s3 * 32 + lane];
                acc4h(a0, v0); acc4h(a1, v1); acc4h(a0, v2); acc4h(a1, v3);
            }
            for (; i < end; i++) {
                uint2 v0 = plane16[(size_t)g_esrc[i] * 32 + lane];
                acc4h(a0, v0);
            }
            float inv = g_inv[node];
            __half2 o0 = __floats2half2_rn((a0.x + a1.x) * inv, (a0.y + a1.y) * inv);
            __half2 o1 = __floats2half2_rn((a0.z + a1.z) * inv, (a0.w + a1.w) * inv);
            g_agg16[(size_t)node * 32 + lane] = make_uint2(*(uint32_t*)&o0, *(uint32_t*)&o1);
        }
        __syncthreads();
        if (tid == 0) {
            __threadfence();
            int tile = (int)blockIdx.x >> 4;   // 16 agg blocks per 128-row tile
            asm volatile("red.release.gpu.global.add.s32 [%0], 1;"
                         :: "l"(&g_tilecnt[layer * 1024 + tile]) : "memory");
        }
        return;
    }

    // ======================= GEMM ROLE =======================
    const uint32_t s0_u = smem_u32(smem);
    const int wid = tid >> 5;
    const int lane = tid & 31;
    const int g = lane >> 2;
    const int tg = lane & 3;
    const int warp_m = wid & 3;
    const int warp_n = wid >> 2;
    const int tile = (int)blockIdx.x - nAgg;
    const int m0 = tile * 128;

    uint32_t offA[2];
    #pragma unroll
    for (int t = 0; t < 2; t++)
        offA[t] = (uint32_t)((warp_m * 32 + t * 16 + (lane & 7)
                   + ((lane >> 3) & 1) * 8) * RS16 + ((lane >> 4) & 1) * 16);
    uint32_t offB[4];
    #pragma unroll
    for (int up = 0; up < 4; up++)
        offB[up] = (uint32_t)(TILE16 + (warp_n * 64 + up * 16 + (lane & 7)
                   + ((lane >> 4) & 1) * 8) * RS16 + ((lane >> 3) & 1) * 16);

    auto stage = [&](int kc) {
        const uint32_t base = s0_u + (kc & 1) * BUF16;
        const char* a16 = (const char*)((kc < 2) ? g_agg16 : plane16);
        const int koffB = (kc & 1) * 128;
        #pragma unroll
        for (int it = 0; it < 4; it++) {
            int i = tid + it * 256;
            int row = i >> 3, q = i & 7;
            int node = m0 + row;
            const char* gp = a16 + (size_t)node * 256 + koffB + q * 16;
            cpasync16(base + row * RS16 + q * 16, gp, (node < nN) ? 16 : 0);
        }
        const char* wsrc = g_W16 + ((size_t)layer * 4 + kc) * 16384;
        #pragma unroll
        for (int it = 0; it < 4; it++) {
            int i = tid + it * 256;
            int n = i >> 3, q = i & 7;
            cpasync16(base + TILE16 + n * RS16 + q * 16, wsrc + n * 128 + q * 16, 16);
        }
        asm volatile("cp.async.commit_group;" ::: "memory");
    };

    float acc[2][8][4];
    #pragma unroll
    for (int t = 0; t < 2; t++)
        #pragma unroll
        for (int u = 0; u < 8; u++)
            #pragma unroll
            for (int c = 0; c < 4; c++) acc[t][u][c] = 0.f;

    auto mma_buf = [&](uint32_t base) {
        #pragma unroll
        for (int ks = 0; ks < 4; ks++) {
            uint32_t a[2][4];
            LDSM4(a[0][0], a[0][1], a[0][2], a[0][3], base + offA[0] + ks * 32);
            LDSM4(a[1][0], a[1][1], a[1][2], a[1][3], base + offA[1] + ks * 32);
            uint32_t b[8][2];
            #pragma unroll
            for (int up = 0; up < 4; up++)
                LDSM4(b[2 * up][0], b[2 * up][1], b[2 * up + 1][0], b[2 * up + 1][1],
                      base + offB[up] + ks * 32);
            #pragma unroll
            for (int u = 0; u < 8; u++)
                #pragma unroll
                for (int t = 0; t < 2; t++)
                    MMA_F16(acc[t][u], a[t][0], a[t][1], a[t][2], a[t][3],
                            b[u][0], b[u][1]);
        }
    };

    // x chunks first (kc 2,3) — independent of aggregation
    stage(2);                                                  // g0 -> buf0
    stage(3);                                                  // g1 -> buf1
    asm volatile("cp.async.wait_group 1;" ::: "memory");       // g0 done
    __syncthreads();
    mma_buf(s0_u);                                             // kc2
    __syncthreads();
    // wait for this tile's aggregation (agg blocks have lower bids -> progress)
    {
        int rem = nN - m0;
        int expected = ((rem < 128 ? rem : 128) + 7) >> 3;
        if (tid == 0) {
            const int* cnt = &g_tilecnt[layer * 1024 + tile];
            int v;
            do {
                asm volatile("ld.acquire.gpu.global.b32 %0, [%1];"
                             : "=r"(v) : "l"(cnt) : "memory");
                if (v < expected) __nanosleep(64);
            } while (v < expected);
        }
        __syncthreads();
    }
    stage(0);                                                  // g2 -> buf0 (mean)
    asm volatile("cp.async.wait_group 1;" ::: "memory");       // g1 done
    __syncthreads();
    mma_buf(s0_u + BUF16);                                     // kc3
    __syncthreads();
    stage(1);                                                  // g3 -> buf1 (mean)
    asm volatile("cp.async.wait_group 1;" ::: "memory");       // g2 done
    __syncthreads();
    mma_buf(s0_u);                                             // kc0
    asm volatile("cp.async.wait_group 0;" ::: "memory");       // g3 done
    __syncthreads();
    mma_buf(s0_u + BUF16);                                     // kc1

    // ---- epilogue ----
    #pragma unroll
    for (int u = 0; u < 8; u++) {
        int cb = warp_n * 64 + u * 8 + 2 * tg;
        float2 bv = *(const float2*)(bias + cb);
        #pragma unroll
        for (int t = 0; t < 2; t++) {
            int r0 = m0 + warp_m * 32 + t * 16 + g;
            float2 o0 = make_float2(acc[t][u][0] + bv.x, acc[t][u][1] + bv.y);
            float2 o1 = make_float2(acc[t][u][2] + bv.x, acc[t][u][3] + bv.y);
            if (RELU) {
                o0.x = fmaxf(o0.x, 0.f); o0.y = fmaxf(o0.y, 0.f);
                o1.x = fmaxf(o1.x, 0.f); o1.y = fmaxf(o1.y, 0.f);
            }
            if (EMIT16) {
                if (r0 < nN) {
                    __half2 p = __floats2half2_rn(o0.x, o0.y);
                    out16[(size_t)r0 * 64 + (cb >> 1)] = *(uint32_t*)&p;
                }
                if (r0 + 8 < nN) {
                    __half2 p = __floats2half2_rn(o1.x, o1.y);
                    out16[(size_t)(r0 + 8) * 64 + (cb >> 1)] = *(uint32_t*)&p;
                }
            } else {
                if (r0 < nN)     *(float2*)(out + (size_t)r0 * 128 + cb) = o0;
                if (r0 + 8 < nN) *(float2*)(out + (size_t)(r0 + 8) * 128 + cb) = o1;
            }
        }
    }
}

// ---------------------------------------------------------------------------
extern "C" void kernel_launch(void* const* d_in, const int* in_sizes, int n_in,
                              void* d_out, int out_size) {
    const float* x   = (const float*)d_in[0];
    const void*  eix = d_in[1];
    const float* Wl1 = (const float*)d_in[2];
    const float* Wr1 = (const float*)d_in[3];
    const float* b1  = (const float*)d_in[4];
    const float* Wl2 = (const float*)d_in[5];
    const float* Wr2 = (const float*)d_in[6];
    const float* b2  = (const float*)d_in[7];
    float* out = (float*)d_out;

    const int nN = in_sizes[0] / D;      // 100000
    const int nE = in_sizes[1] / 2;      // 1600000

    void *degp, *x16p, *h16p, *cntp;
    cudaGetSymbolAddress(&degp, g_deg);
    cudaGetSymbolAddress(&x16p, g_x16);
    cudaGetSymbolAddress(&h16p, g_h16);
    cudaGetSymbolAddress(&cntp, g_tilecnt);

    cudaFuncSetAttribute(layer_kernel<true, true>,
                         cudaFuncAttributeMaxDynamicSharedMemorySize, SM_TOTAL);
    cudaFuncSetAttribute(layer_kernel<false, false>,
                         cudaFuncAttributeMaxDynamicSharedMemorySize, SM_TOTAL);

    const int edgeGrpBlocks = ((nE / 4 + 1) + 255) / 256;
    const int gemmBlocks = (nN + 127) / 128;          // 782 tiles
    const int aggBlocks  = (nN + 7) / 8;              // 12500
    const int scanBlocks = (nN + 1023) / 1024;        // 98
    const int n4 = nN * 32;
    const int convBlocks = (n4 + 255) / 256;

    // ---- CSR build + weight/x fp16 conversion + flag reset ----
    cudaMemsetAsync(degp, 0, (size_t)nN * sizeof(int));
    cudaMemsetAsync(cntp, 0, sizeof(g_tilecnt));
    detect_kernel<<<1, 1>>>(eix);
    wconv16_kernel<<<4, 256>>>(Wl1, Wr1, Wl2, Wr2);
    tohalf_kernel<<<convBlocks, 256>>>((const float4*)x, (uint2*)x16p, n4);
    deg_kernel<<<edgeGrpBlocks, 256>>>(eix, nE);
    blocksum_kernel<<<scanBlocks, 256>>>(nN);
    scanpart_kernel<<<1, 128>>>(scanBlocks);
    offsets_kernel<<<scanBlocks, 256>>>(nN, nE);
    fill_kernel<<<edgeGrpBlocks, 256>>>(eix, nE);

    // ---- layer 1: merged agg+gemm (emits fp16 plane h16) ----
    layer_kernel<true, true><<<aggBlocks + gemmBlocks, 256, SM_TOTAL>>>(
        (const uint2*)x16p, 0, b1, nullptr, (uint32_t*)h16p, nN, aggBlocks);

    // ---- layer 2: merged agg+gemm (fp32 output) ----
    layer_kernel<false, false><<<aggBlocks + gemmBlocks, 256, SM_TOTAL>>>(
        (const uint2*)h16p, 1, b2, out, nullptr, nN, aggBlocks);
}